// round 15
// baseline (speedup 1.0000x reference)
#include <cuda_runtime.h>
#include <cuda_bf16.h>
#include <math.h>
#include <stdint.h>

// ----------------------------------------------------------------------------
// TransformerLayer: B=2, L=2048, D=1024, H=16, HD=64, FF=4096
// R8 champion pipeline (bf16x3 HMMA, pre-split pair-packed operands,
// cp.async double-buffered GEMM, 2 CTAs/SM) + NEW: w1 column-interleave with
// GeGLU fused into GEMM-6 epilogue (u fp32 round-trip eliminated).
// ----------------------------------------------------------------------------

#define NTOK   4096
#define DMODEL 1024
#define NHEAD  16
#define HDIM   64
#define FFDIM  4096
#define SEQ    2048

// Weight split offsets (u32 pair units). Layout: W[k/2][N] pair-packed.
#define OFF_WQKV 0
#define OFF_WOUT (512 * 3072)
#define OFF_W1   (OFF_WOUT + 512 * 1024)
#define OFF_W2   (OFF_W1 + 512 * 8192)
#define WTOT     (OFF_W2 + 2048 * 1024)

__device__ uint32_t g_wh[WTOT];
__device__ uint32_t g_wl[WTOT];
__device__ uint32_t g_ah[(size_t)NTOK * 2048];   // activation A (pair-packed)
__device__ uint32_t g_al[(size_t)NTOK * 2048];
__device__ uint32_t g_qh[(size_t)NTOK * 1536];   // qkv (pair-packed, Q pre-scaled)
__device__ uint32_t g_ql[(size_t)NTOK * 1536];
__device__ uint16_t g_gh[(size_t)NTOK * FFDIM];  // geglu out bf16 hi (33MB)
__device__ uint16_t g_gl[(size_t)NTOK * FFDIM];  // geglu out bf16 lo
__device__ float    g_p [(size_t)NTOK * DMODEL];
__device__ float    g_b1i[2 * FFDIM];            // interleaved b1

// ---------------------------------------------------------------------------
__device__ __forceinline__ void split2(float x, float y,
                                       uint32_t& hi, uint32_t& lo) {
    __nv_bfloat162 h = __floats2bfloat162_rn(x, y);
    float lx = x - __bfloat162float(h.x);
    float ly = y - __bfloat162float(h.y);
    __nv_bfloat162 l = __floats2bfloat162_rn(lx, ly);
    hi = *(uint32_t*)&h;
    lo = *(uint32_t*)&l;
}

__device__ __forceinline__ void split1(float x, uint16_t& hi, uint16_t& lo) {
    __nv_bfloat16 h = __float2bfloat16(x);
    float l = x - __bfloat162float(h);
    __nv_bfloat16 lb = __float2bfloat16(l);
    hi = *(uint16_t*)&h;
    lo = *(uint16_t*)&lb;
}

__device__ __forceinline__ void mma_bf16(float c[4], const uint32_t a[4],
                                         uint32_t b0, uint32_t b1) {
    asm volatile(
        "mma.sync.aligned.m16n8k16.row.col.f32.bf16.bf16.f32 "
        "{%0,%1,%2,%3}, {%4,%5,%6,%7}, {%8,%9}, {%0,%1,%2,%3};"
        : "+f"(c[0]), "+f"(c[1]), "+f"(c[2]), "+f"(c[3])
        : "r"(a[0]), "r"(a[1]), "r"(a[2]), "r"(a[3]), "r"(b0), "r"(b1));
}

#define CP16(smem_u32_addr, gptr) \
    asm volatile("cp.async.cg.shared.global [%0], [%1], 16;" \
                 :: "r"(smem_u32_addr), "l"(gptr))
#define CP_COMMIT() asm volatile("cp.async.commit_group;")
#define CP_WAIT1()  asm volatile("cp.async.wait_group 1;")
#define CP_WAIT0()  asm volatile("cp.async.wait_group 0;")

// ---------------------------------------------------------------------------
// Weight split: W[K,N] fp32 -> pair-packed hi/lo [K/2][N] u32
// ---------------------------------------------------------------------------
__global__ __launch_bounds__(256) void split_w_kernel(
    const float* __restrict__ W, uint32_t* __restrict__ Wh,
    uint32_t* __restrict__ Wl, int N, int total)   // total = (K/2)*(N/4)
{
    int idx = blockIdx.x * 256 + threadIdx.x;
    if (idx >= total) return;
    int nc4 = N >> 2;
    int kp = idx / nc4;
    int nc = (idx - kp * nc4) * 4;
    const float4 r0 = *(const float4*)(W + (size_t)(2 * kp) * N + nc);
    const float4 r1 = *(const float4*)(W + (size_t)(2 * kp + 1) * N + nc);
    uint32_t h0,l0,h1,l1,h2,l2,h3,l3;
    split2(r0.x, r1.x, h0, l0);
    split2(r0.y, r1.y, h1, l1);
    split2(r0.z, r1.z, h2, l2);
    split2(r0.w, r1.w, h3, l3);
    size_t o = (size_t)kp * N + nc;
    *(uint4*)(Wh + o) = make_uint4(h0, h1, h2, h3);
    *(uint4*)(Wl + o) = make_uint4(l0, l1, l2, l3);
}

// w1 split with column interleave: new col 2j = old j (a), 2j+1 = old FF+j (g)
__global__ __launch_bounds__(256) void split_w1_kernel(
    const float* __restrict__ W, uint32_t* __restrict__ Wh,
    uint32_t* __restrict__ Wl)
{
    int idx = blockIdx.x * 256 + threadIdx.x;   // 512 * 2048 total
    int kp = idx >> 11;
    int nc = (idx & 2047) * 4;
    const float* W0 = W + (size_t)(2 * kp) * (2 * FFDIM);
    const float* W1 = W0 + 2 * FFDIM;
    size_t o = (size_t)kp * (2 * FFDIM) + nc;
    #pragma unroll
    for (int e = 0; e < 4; e++) {
        int nn = nc + e;
        int src = (nn & 1) ? (FFDIM + (nn >> 1)) : (nn >> 1);
        uint32_t h, l;
        split2(W0[src], W1[src], h, l);
        Wh[o + e] = h;
        Wl[o + e] = l;
    }
}

__global__ __launch_bounds__(256) void interleave_b1_kernel(
    const float* __restrict__ b1, float* __restrict__ b1i)
{
    int i = blockIdx.x * 256 + threadIdx.x;     // 8192
    b1i[i] = b1[(i & 1) ? (FFDIM + (i >> 1)) : (i >> 1)];
}

// ---------------------------------------------------------------------------
__device__ __forceinline__ float2 block_reduce2_256(float a, float b) {
    #pragma unroll
    for (int o = 16; o > 0; o >>= 1) {
        a += __shfl_xor_sync(0xffffffffu, a, o);
        b += __shfl_xor_sync(0xffffffffu, b, o);
    }
    __shared__ float sa[8], sb[8];
    int w = threadIdx.x >> 5, lane = threadIdx.x & 31;
    __syncthreads();
    if (lane == 0) { sa[w] = a; sb[w] = b; }
    __syncthreads();
    float ta = 0.f, tb = 0.f;
    #pragma unroll
    for (int i = 0; i < 8; i++) { ta += sa[i]; tb += sb[i]; }
    return make_float2(ta, tb);
}

__global__ __launch_bounds__(256) void ln_kernel(
    const float* __restrict__ in, const float* __restrict__ g,
    const float* __restrict__ b,
    uint32_t* __restrict__ outH, uint32_t* __restrict__ outL)
{
    int row = blockIdx.x;
    int t = threadIdx.x;
    const float4 v = ((const float4*)(in + (size_t)row * DMODEL))[t];
    float s = v.x + v.y + v.z + v.w;
    float q = v.x*v.x + v.y*v.y + v.z*v.z + v.w*v.w;
    float2 r = block_reduce2_256(s, q);
    const float inv_n = 1.0f / DMODEL;
    float mu  = r.x * inv_n;
    float var = r.y * inv_n - mu * mu;
    float inv = rsqrtf(var + 1e-5f);
    const float4 gg = ((const float4*)g)[t];
    const float4 bb = ((const float4*)b)[t];
    float o0 = (v.x - mu) * inv * gg.x + bb.x;
    float o1 = (v.y - mu) * inv * gg.y + bb.y;
    float o2 = (v.z - mu) * inv * gg.z + bb.z;
    float o3 = (v.w - mu) * inv * gg.w + bb.w;
    uint32_t h0,l0,h1,l1;
    split2(o0, o1, h0, l0);
    split2(o2, o3, h1, l1);
    ((uint2*)(outH + (size_t)row * 512))[t] = make_uint2(h0, h1);
    ((uint2*)(outL + (size_t)row * 512))[t] = make_uint2(l0, l1);
}

__global__ __launch_bounds__(256) void dln_kernel(
    const float* __restrict__ in,
    const float* __restrict__ g1, const float* __restrict__ b1,
    const float* __restrict__ sc,
    const float* __restrict__ g2, const float* __restrict__ b2,
    uint32_t* __restrict__ outH, uint32_t* __restrict__ outL)
{
    int row = blockIdx.x;
    int t = threadIdx.x;
    const float inv_n = 1.0f / DMODEL;
    const float4 v = ((const float4*)(in + (size_t)row * DMODEL))[t];
    float s = v.x + v.y + v.z + v.w;
    float q = v.x*v.x + v.y*v.y + v.z*v.z + v.w*v.w;
    float2 r = block_reduce2_256(s, q);
    float mu  = r.x * inv_n;
    float var = r.y * inv_n - mu * mu;
    float inv = rsqrtf(var + 1e-5f);
    const float4 gg1 = ((const float4*)g1)[t];
    const float4 bb1 = ((const float4*)b1)[t];
    const float4 sc4 = ((const float4*)sc)[t];
    float4 tv;
    tv.x = ((v.x - mu) * inv * gg1.x + bb1.x) * sc4.x;
    tv.y = ((v.y - mu) * inv * gg1.y + bb1.y) * sc4.y;
    tv.z = ((v.z - mu) * inv * gg1.z + bb1.z) * sc4.z;
    tv.w = ((v.w - mu) * inv * gg1.w + bb1.w) * sc4.w;
    float s2 = tv.x + tv.y + tv.z + tv.w;
    float q2 = tv.x*tv.x + tv.y*tv.y + tv.z*tv.z + tv.w*tv.w;
    float2 r2 = block_reduce2_256(s2, q2);
    float mu2  = r2.x * inv_n;
    float var2 = r2.y * inv_n - mu2 * mu2;
    float inv2 = rsqrtf(var2 + 1e-5f);
    const float4 gg2 = ((const float4*)g2)[t];
    const float4 bb2 = ((const float4*)b2)[t];
    float o0 = (tv.x - mu2) * inv2 * gg2.x + bb2.x;
    float o1 = (tv.y - mu2) * inv2 * gg2.y + bb2.y;
    float o2 = (tv.z - mu2) * inv2 * gg2.z + bb2.z;
    float o3 = (tv.w - mu2) * inv2 * gg2.w + bb2.w;
    uint32_t h0,l0,h1,l1;
    split2(o0, o1, h0, l0);
    split2(o2, o3, h1, l1);
    ((uint2*)(outH + (size_t)row * 512))[t] = make_uint2(h0, h1);
    ((uint2*)(outL + (size_t)row * 512))[t] = make_uint2(l0, l1);
}

// ---------------------------------------------------------------------------
// bf16x3 GEMM (exact R8 mainloop) + epilogue variants:
//   Cf  != 0 : fp32 out (+bias)(*cscale)(Q-scale cols)
//   Ch  != 0 : pair-packed bf16 hi/lo out
//   G16h!= 0 : fused GeGLU (interleaved cols): out[c] = a*g*Phi(g), bf16 hi/lo
// ---------------------------------------------------------------------------
__global__ __launch_bounds__(256, 2) void gemm_ps_kernel(
    const uint32_t* __restrict__ Ah, const uint32_t* __restrict__ Al, int ldap,
    const uint32_t* __restrict__ Bh, const uint32_t* __restrict__ Bl,
    const float* __restrict__ bias, const float* __restrict__ cscale,
    float* __restrict__ Cf, uint32_t* __restrict__ Ch, uint32_t* __restrict__ Cl,
    uint16_t* __restrict__ G16h, uint16_t* __restrict__ G16l,
    int qscaleCols, int M, int N, int K)
{
    __shared__ uint32_t AhS[2][128][20];
    __shared__ uint32_t AlS[2][128][20];
    __shared__ uint32_t BhS[2][16][136];
    __shared__ uint32_t BlS[2][16][136];

    const int tid  = threadIdx.x;
    const int warp = tid >> 5;
    const int lane = tid & 31;
    const int wm = (warp & 3) * 32;
    const int wn = (warp >> 2) * 64;
    const int q  = lane >> 2;
    const int r  = lane & 3;

    const int rowBase = blockIdx.y * 128;
    const int colBase = blockIdx.x * 128;

    const int arow0 = tid >> 2;
    const int acc0  = (tid & 3) * 4;
    const int bkp0  = tid >> 5;
    const int bcc0  = (tid & 31) * 4;

    const int nt = K >> 5;

    auto issue = [&](int st, int bb) {
        int kp0 = st * 16;
        #pragma unroll
        for (int it = 0; it < 2; it++) {
            int row = arow0 + 64 * it;
            size_t src = (size_t)(rowBase + row) * ldap + kp0 + acc0;
            uint32_t d1 = (uint32_t)__cvta_generic_to_shared(&AhS[bb][row][acc0]);
            uint32_t d2 = (uint32_t)__cvta_generic_to_shared(&AlS[bb][row][acc0]);
            CP16(d1, Ah + src);
            CP16(d2, Al + src);
        }
        #pragma unroll
        for (int it = 0; it < 2; it++) {
            int kp = bkp0 + 8 * it;
            size_t src = (size_t)(kp0 + kp) * N + colBase + bcc0;
            uint32_t d1 = (uint32_t)__cvta_generic_to_shared(&BhS[bb][kp][bcc0]);
            uint32_t d2 = (uint32_t)__cvta_generic_to_shared(&BlS[bb][kp][bcc0]);
            CP16(d1, Bh + src);
            CP16(d2, Bl + src);
        }
        CP_COMMIT();
    };

    float c[2][8][4];
    #pragma unroll
    for (int mf = 0; mf < 2; mf++)
        #pragma unroll
        for (int nf = 0; nf < 8; nf++)
            #pragma unroll
            for (int e = 0; e < 4; e++) c[mf][nf][e] = 0.f;

    issue(0, 0);

    for (int i = 0; i < nt; i++) {
        const int bb = i & 1;
        if (i + 1 < nt) { issue(i + 1, bb ^ 1); CP_WAIT1(); }
        else            { CP_WAIT0(); }
        __syncthreads();

        #pragma unroll
        for (int ks = 0; ks < 2; ks++) {
            const int kk2 = ks * 8;
            uint32_t ah[2][4], al[2][4];
            #pragma unroll
            for (int mf = 0; mf < 2; mf++) {
                int m0 = wm + mf * 16 + q;
                ah[mf][0] = AhS[bb][m0    ][kk2 + r];
                ah[mf][1] = AhS[bb][m0 + 8][kk2 + r];
                ah[mf][2] = AhS[bb][m0    ][kk2 + 4 + r];
                ah[mf][3] = AhS[bb][m0 + 8][kk2 + 4 + r];
                al[mf][0] = AlS[bb][m0    ][kk2 + r];
                al[mf][1] = AlS[bb][m0 + 8][kk2 + r];
                al[mf][2] = AlS[bb][m0    ][kk2 + 4 + r];
                al[mf][3] = AlS[bb][m0 + 8][kk2 + 4 + r];
            }
            #pragma unroll
            for (int nf = 0; nf < 8; nf++) {
                int n = wn + nf * 8 + q;
                uint32_t bh0 = BhS[bb][kk2 + r    ][n];
                uint32_t bh1 = BhS[bb][kk2 + 4 + r][n];
                uint32_t bl0 = BlS[bb][kk2 + r    ][n];
                uint32_t bl1 = BlS[bb][kk2 + 4 + r][n];
                #pragma unroll
                for (int mf = 0; mf < 2; mf++) {
                    mma_bf16(c[mf][nf], ah[mf], bh0, bh1);
                    mma_bf16(c[mf][nf], al[mf], bh0, bh1);
                    mma_bf16(c[mf][nf], ah[mf], bl0, bl1);
                }
            }
        }
        __syncthreads();
    }

    // ---- epilogue ----
    #pragma unroll
    for (int mf = 0; mf < 2; mf++) {
        int row0 = rowBase + wm + mf * 16 + q;
        #pragma unroll
        for (int half = 0; half < 2; half++) {
            int row = row0 + half * 8;
            #pragma unroll
            for (int nf = 0; nf < 8; nf++) {
                int col = colBase + wn + nf * 8 + r * 2;
                float v0 = c[mf][nf][half * 2 + 0];
                float v1 = c[mf][nf][half * 2 + 1];
                if (bias)   { v0 += bias[col];   v1 += bias[col + 1]; }
                if (col < qscaleCols) { v0 *= 0.125f; v1 *= 0.125f; }
                if (Cf) {
                    if (cscale) { v0 *= cscale[col]; v1 *= cscale[col + 1]; }
                    *(float2*)(Cf + (size_t)row * N + col) = make_float2(v0, v1);
                } else if (Ch) {
                    uint32_t hh, ll;
                    split2(v0, v1, hh, ll);
                    size_t off = (size_t)row * (N >> 1) + (col >> 1);
                    Ch[off] = hh;
                    Cl[off] = ll;
                } else {
                    // fused GeGLU: v0 = a, v1 = g (interleaved w1 columns)
                    float ov = v0 * v1 * normcdff(v1);
                    uint16_t hh, ll;
                    split1(ov, hh, ll);
                    size_t off = (size_t)row * (N >> 1) + (col >> 1);
                    G16h[off] = hh;
                    G16l[off] = ll;
                }
            }
        }
    }
}

// ---------------------------------------------------------------------------
// bf16x3 HMMA flash attention (validated R8, unchanged).
// ---------------------------------------------------------------------------
__global__ __launch_bounds__(256) void attn_tc_kernel(
    const uint32_t* __restrict__ qkvh, const uint32_t* __restrict__ qkvl,
    uint32_t* __restrict__ outH, uint32_t* __restrict__ outL)
{
    __shared__ uint32_t KpH[64][36];
    __shared__ uint32_t KpL[64][36];
    __shared__ uint32_t VpH[32][72];
    __shared__ uint32_t VpL[32][72];

    const int bh = blockIdx.y;
    const int b  = bh >> 4;
    const int h  = bh & 15;
    const int tid  = threadIdx.x;
    const int warp = tid >> 5;
    const int lane = tid & 31;
    const int q = lane >> 2;
    const int r = lane & 3;

    const int qrow = blockIdx.x * 128 + warp * 16;

    uint32_t qh[4][4], ql[4][4];
    {
        const uint32_t* Q0h = qkvh + (size_t)(b * SEQ + qrow + q) * 1536 + 32 * h;
        const uint32_t* Q1h = Q0h + 8 * 1536;
        const uint32_t* Q0l = qkvl + (size_t)(b * SEQ + qrow + q) * 1536 + 32 * h;
        const uint32_t* Q1l = Q0l + 8 * 1536;
        #pragma unroll
        for (int ks = 0; ks < 4; ks++) {
            int p = 8 * ks + r;
            qh[ks][0] = Q0h[p];     qh[ks][1] = Q1h[p];
            qh[ks][2] = Q0h[p + 4]; qh[ks][3] = Q1h[p + 4];
            ql[ks][0] = Q0l[p];     ql[ks][1] = Q1l[p];
            ql[ks][2] = Q0l[p + 4]; ql[ks][3] = Q1l[p + 4];
        }
    }

    float o[8][4];
    #pragma unroll
    for (int nf = 0; nf < 8; nf++)
        #pragma unroll
        for (int e = 0; e < 4; e++) o[nf][e] = 0.f;
    float m0 = -1e30f, m1 = -1e30f;
    float l0 = 0.f, l1 = 0.f;

    const size_t baseK = (size_t)(b * SEQ) * 1536 + 512 + 32 * h;
    const size_t baseV = (size_t)(b * SEQ) * 1536 + 1024 + 32 * h;

    for (int j0 = 0; j0 < SEQ; j0 += 64) {
        __syncthreads();
        #pragma unroll
        for (int it = 0; it < 2; it++) {
            int idx = tid + it * 256;
            int key = idx >> 3;
            int c   = (idx & 7) * 4;
            size_t src = baseK + (size_t)(j0 + key) * 1536 + c;
            *(uint4*)&KpH[key][c] = *(const uint4*)(qkvh + src);
            *(uint4*)&KpL[key][c] = *(const uint4*)(qkvl + src);
        }
        #pragma unroll
        for (int it = 0; it < 2; it++) {
            int idx = tid + it * 256;
            int kp  = idx >> 4;
            int dpp = (idx & 15) * 2;
            size_t src = baseV + (size_t)(j0 + 2 * kp) * 1536 + dpp;
            uint2 aH = *(const uint2*)(qkvh + src);
            uint2 bH = *(const uint2*)(qkvh + src + 1536);
            uint2 aL = *(const uint2*)(qkvl + src);
            uint2 bL = *(const uint2*)(qkvl + src + 1536);
            VpH[kp][2*dpp    ] = __byte_perm(aH.x, bH.x, 0x5410);
            VpH[kp][2*dpp + 1] = __byte_perm(aH.x, bH.x, 0x7632);
            VpH[kp][2*dpp + 2] = __byte_perm(aH.y, bH.y, 0x5410);
            VpH[kp][2*dpp + 3] = __byte_perm(aH.y, bH.y, 0x7632);
            VpL[kp][2*dpp    ] = __byte_perm(aL.x, bL.x, 0x5410);
            VpL[kp][2*dpp + 1] = __byte_perm(aL.x, bL.x, 0x7632);
            VpL[kp][2*dpp + 2] = __byte_perm(aL.y, bL.y, 0x5410);
            VpL[kp][2*dpp + 3] = __byte_perm(aL.y, bL.y, 0x7632);
        }
        __syncthreads();

        float s[8][4];
        #pragma unroll
        for (int nf = 0; nf < 8; nf++)
            #pragma unroll
            for (int e = 0; e < 4; e++) s[nf][e] = 0.f;

        #pragma unroll
        for (int ks = 0; ks < 4; ks++) {
            #pragma unroll
            for (int nf = 0; nf < 8; nf++) {
                int key = 8 * nf + q;
                uint32_t bh0 = KpH[key][8 * ks + r];
                uint32_t bh1 = KpH[key][8 * ks + r + 4];
                uint32_t bl0 = KpL[key][8 * ks + r];
                uint32_t bl1 = KpL[key][8 * ks + r + 4];
                mma_bf16(s[nf], qh[ks], bh0, bh1);
                mma_bf16(s[nf], ql[ks], bh0, bh1);
                mma_bf16(s[nf], qh[ks], bl0, bl1);
            }
        }

        float t0 = -1e30f, t1 = -1e30f;
        #pragma unroll
        for (int nf = 0; nf < 8; nf++) {
            t0 = fmaxf(t0, fmaxf(s[nf][0], s[nf][1]));
            t1 = fmaxf(t1, fmaxf(s[nf][2], s[nf][3]));
        }
        t0 = fmaxf(t0, __shfl_xor_sync(0xffffffffu, t0, 1));
        t0 = fmaxf(t0, __shfl_xor_sync(0xffffffffu, t0, 2));
        t1 = fmaxf(t1, __shfl_xor_sync(0xffffffffu, t1, 1));
        t1 = fmaxf(t1, __shfl_xor_sync(0xffffffffu, t1, 2));

        float mn0 = fmaxf(m0, t0), mn1 = fmaxf(m1, t1);
        float a0 = __expf(m0 - mn0), a1 = __expf(m1 - mn1);
        m0 = mn0; m1 = mn1;
        l0 *= a0; l1 *= a1;
        #pragma unroll
        for (int nf = 0; nf < 8; nf++) {
            o[nf][0] *= a0; o[nf][1] *= a0;
            o[nf][2] *= a1; o[nf][3] *= a1;
        }

        uint32_t pah[4][4], pal[4][4];
        float sum0 = 0.f, sum1 = 0.f;
        #pragma unroll
        for (int nf = 0; nf < 8; nf++) {
            float p0 = __expf(s[nf][0] - m0);
            float p1 = __expf(s[nf][1] - m0);
            float p2 = __expf(s[nf][2] - m1);
            float p3 = __expf(s[nf][3] - m1);
            sum0 += p0 + p1; sum1 += p2 + p3;
            int ks = nf >> 1, part = nf & 1;
            split2(p0, p1, pah[ks][2 * part],     pal[ks][2 * part]);
            split2(p2, p3, pah[ks][2 * part + 1], pal[ks][2 * part + 1]);
        }
        sum0 += __shfl_xor_sync(0xffffffffu, sum0, 1);
        sum0 += __shfl_xor_sync(0xffffffffu, sum0, 2);
        sum1 += __shfl_xor_sync(0xffffffffu, sum1, 1);
        sum1 += __shfl_xor_sync(0xffffffffu, sum1, 2);
        l0 += sum0; l1 += sum1;

        #pragma unroll
        for (int ks = 0; ks < 4; ks++) {
            #pragma unroll
            for (int nf = 0; nf < 8; nf++) {
                int d = 8 * nf + q;
                uint32_t bh0 = VpH[8 * ks + r    ][d];
                uint32_t bh1 = VpH[8 * ks + r + 4][d];
                uint32_t bl0 = VpL[8 * ks + r    ][d];
                uint32_t bl1 = VpL[8 * ks + r + 4][d];
                mma_bf16(o[nf], pah[ks], bh0, bh1);
                mma_bf16(o[nf], pal[ks], bh0, bh1);
                mma_bf16(o[nf], pah[ks], bl0, bl1);
            }
        }
    }

    float inv0 = 1.0f / l0, inv1 = 1.0f / l1;
    uint32_t* O0h = outH + (size_t)(b * SEQ + qrow + q) * 512 + 32 * h;
    uint32_t* O0l = outL + (size_t)(b * SEQ + qrow + q) * 512 + 32 * h;
    uint32_t* O1h = O0h + 8 * 512;
    uint32_t* O1l = O0l + 8 * 512;
    #pragma unroll
    for (int nf = 0; nf < 8; nf++) {
        int pc = 4 * nf + r;
        uint32_t hh, ll;
        split2(o[nf][0] * inv0, o[nf][1] * inv0, hh, ll);
        O0h[pc] = hh; O0l[pc] = ll;
        split2(o[nf][2] * inv1, o[nf][3] * inv1, hh, ll);
        O1h[pc] = hh; O1l[pc] = ll;
    }
}

// ---------------------------------------------------------------------------
extern "C" void kernel_launch(void* const* d_in, const int* in_sizes, int n_in,
                              void* d_out, int out_size)
{
    const float* x            = (const float*)d_in[0];
    const float* w_qkv        = (const float*)d_in[2];
    const float* w_out        = (const float*)d_in[3];
    const float* b_out        = (const float*)d_in[4];
    const float* ln_inner_g   = (const float*)d_in[5];
    const float* ln_inner_b   = (const float*)d_in[6];
    const float* ln_pre_attn_g= (const float*)d_in[7];
    const float* ln_pre_attn_b= (const float*)d_in[8];
    const float* scale_attn   = (const float*)d_in[9];
    const float* w1           = (const float*)d_in[10];
    const float* b1           = (const float*)d_in[11];
    const float* w2           = (const float*)d_in[12];
    const float* b2           = (const float*)d_in[13];
    const float* ln_pre_ff_g  = (const float*)d_in[14];
    const float* ln_pre_ff_b  = (const float*)d_in[15];
    const float* scale_ff     = (const float*)d_in[16];
    float* out = (float*)d_out;

    uint32_t *whP, *wlP, *ahP, *alP, *qhP, *qlP;
    uint16_t *ghP, *glP;
    float *pP, *b1iP;
    cudaGetSymbolAddress((void**)&whP, g_wh);
    cudaGetSymbolAddress((void**)&wlP, g_wl);
    cudaGetSymbolAddress((void**)&ahP, g_ah);
    cudaGetSymbolAddress((void**)&alP, g_al);
    cudaGetSymbolAddress((void**)&qhP, g_qh);
    cudaGetSymbolAddress((void**)&qlP, g_ql);
    cudaGetSymbolAddress((void**)&ghP, g_gh);
    cudaGetSymbolAddress((void**)&glP, g_gl);
    cudaGetSymbolAddress((void**)&pP,  g_p);
    cudaGetSymbolAddress((void**)&b1iP, g_b1i);

    // 0) split weights into pair-packed bf16 hi/lo ([K/2][N] layout)
    {
        int t;
        t = 512 * (3072 / 4);
        split_w_kernel<<<(t + 255) / 256, 256>>>(w_qkv, whP + OFF_WQKV, wlP + OFF_WQKV, 3072, t);
        t = 512 * (1024 / 4);
        split_w_kernel<<<(t + 255) / 256, 256>>>(w_out, whP + OFF_WOUT, wlP + OFF_WOUT, 1024, t);
        // w1: column-interleaved split (a/g adjacent) for fused GeGLU
        split_w1_kernel<<<(512 * 2048) / 256, 256>>>(w1, whP + OFF_W1, wlP + OFF_W1);
        interleave_b1_kernel<<<(2 * FFDIM) / 256, 256>>>(b1, b1iP);
        t = 2048 * (1024 / 4);
        split_w_kernel<<<(t + 255) / 256, 256>>>(w2, whP + OFF_W2, wlP + OFF_W2, 1024, t);
    }

    // 1) h = LN_pre_attn(x) -> packed
    ln_kernel<<<NTOK, 256>>>(x, ln_pre_attn_g, ln_pre_attn_b, ahP, alP);

    // 2) qkv = h @ w_qkv -> packed (Q cols pre-scaled by 0.125)
    gemm_ps_kernel<<<dim3(3072/128, NTOK/128), 256>>>(
        ahP, alP, 512, whP + OFF_WQKV, wlP + OFF_WQKV,
        nullptr, nullptr, nullptr, qhP, qlP, nullptr, nullptr,
        1024, NTOK, 3072, DMODEL);

    // 3) attention -> packed g_ah/g_al
    attn_tc_kernel<<<dim3(SEQ/128, 2 * NHEAD), 256>>>(qhP, qlP, ahP, alP);

    // 4) proj = attn @ w_out + b_out -> fp32 g_p
    gemm_ps_kernel<<<dim3(DMODEL/128, NTOK/128), 256>>>(
        ahP, alP, 512, whP + OFF_WOUT, wlP + OFF_WOUT,
        b_out, nullptr, pP, nullptr, nullptr, nullptr, nullptr,
        0, NTOK, DMODEL, DMODEL);

    // 5) h2 = LN_pre_ff(LN_inner(p) * scale_attn) -> packed
    dln_kernel<<<NTOK, 256>>>(pP, ln_inner_g, ln_inner_b, scale_attn,
                              ln_pre_ff_g, ln_pre_ff_b, ahP, alP);

    // 6) u = h2 @ w1i + b1i, fused GeGLU -> bf16 hi/lo g_gh/g_gl
    gemm_ps_kernel<<<dim3(2*FFDIM/128, NTOK/128), 256>>>(
        ahP, alP, 512, whP + OFF_W1, wlP + OFF_W1,
        b1iP, nullptr, nullptr, nullptr, nullptr, ghP, glP,
        0, NTOK, 2 * FFDIM, DMODEL);

    // 7) out = geglu @ w2 + b2, * scale_ff -> d_out
    gemm_ps_kernel<<<dim3(DMODEL/128, NTOK/128), 256>>>(
        (const uint32_t*)ghP, (const uint32_t*)glP, 2048, whP + OFF_W2, wlP + OFF_W2,
        b2, scale_ff, out, nullptr, nullptr, nullptr, nullptr,
        0, NTOK, DMODEL, FFDIM);
}

// round 16
// speedup vs baseline: 1.5326x; 1.5326x over previous
#include <cuda_runtime.h>
#include <cuda_bf16.h>
#include <math.h>
#include <stdint.h>

// ----------------------------------------------------------------------------
// TransformerLayer: B=2, L=2048, D=1024, H=16, HD=64, FF=4096
// R8 champion pipeline (bf16x3 HMMA, pre-split pair-packed operands,
// 2 CTAs/SM GEMM) with ONE change: 3-stage cp.async ring in the GEMM
// (one __syncthreads per k-tile instead of two). Everything else verbatim R8.
// ----------------------------------------------------------------------------

#define NTOK   4096
#define DMODEL 1024
#define NHEAD  16
#define HDIM   64
#define FFDIM  4096
#define SEQ    2048

// Weight split offsets (u32 pair units). Layout: W[k/2][N] pair-packed.
#define OFF_WQKV 0
#define OFF_WOUT (512 * 3072)
#define OFF_W1   (OFF_WOUT + 512 * 1024)
#define OFF_W2   (OFF_W1 + 512 * 8192)
#define WTOT     (OFF_W2 + 2048 * 1024)

__device__ uint32_t g_wh[WTOT];
__device__ uint32_t g_wl[WTOT];
__device__ uint32_t g_ah[(size_t)NTOK * 2048];   // activation A (pair-packed)
__device__ uint32_t g_al[(size_t)NTOK * 2048];
__device__ uint32_t g_qh[(size_t)NTOK * 1536];   // qkv (pair-packed, Q pre-scaled)
__device__ uint32_t g_ql[(size_t)NTOK * 1536];
__device__ float    g_u [(size_t)NTOK * 2 * FFDIM];
__device__ float    g_p [(size_t)NTOK * DMODEL];

// ---------------------------------------------------------------------------
__device__ __forceinline__ void split2(float x, float y,
                                       uint32_t& hi, uint32_t& lo) {
    __nv_bfloat162 h = __floats2bfloat162_rn(x, y);
    float lx = x - __bfloat162float(h.x);
    float ly = y - __bfloat162float(h.y);
    __nv_bfloat162 l = __floats2bfloat162_rn(lx, ly);
    hi = *(uint32_t*)&h;
    lo = *(uint32_t*)&l;
}

__device__ __forceinline__ void mma_bf16(float c[4], const uint32_t a[4],
                                         uint32_t b0, uint32_t b1) {
    asm volatile(
        "mma.sync.aligned.m16n8k16.row.col.f32.bf16.bf16.f32 "
        "{%0,%1,%2,%3}, {%4,%5,%6,%7}, {%8,%9}, {%0,%1,%2,%3};"
        : "+f"(c[0]), "+f"(c[1]), "+f"(c[2]), "+f"(c[3])
        : "r"(a[0]), "r"(a[1]), "r"(a[2]), "r"(a[3]), "r"(b0), "r"(b1));
}

#define CP16(smem_u32_addr, gptr) \
    asm volatile("cp.async.cg.shared.global [%0], [%1], 16;" \
                 :: "r"(smem_u32_addr), "l"(gptr))
#define CP_COMMIT() asm volatile("cp.async.commit_group;")
#define CP_WAIT1()  asm volatile("cp.async.wait_group 1;")
#define CP_WAIT0()  asm volatile("cp.async.wait_group 0;")

__device__ __forceinline__ uint32_t smem_addr_u32(const void* p) {
    return (uint32_t)__cvta_generic_to_shared(p);
}

// ---------------------------------------------------------------------------
// Weight split: W[K,N] fp32 -> pair-packed hi/lo [K/2][N] u32
// ---------------------------------------------------------------------------
__global__ __launch_bounds__(256) void split_w_kernel(
    const float* __restrict__ W, uint32_t* __restrict__ Wh,
    uint32_t* __restrict__ Wl, int N, int total)   // total = (K/2)*(N/4)
{
    int idx = blockIdx.x * 256 + threadIdx.x;
    if (idx >= total) return;
    int nc4 = N >> 2;
    int kp = idx / nc4;
    int nc = (idx - kp * nc4) * 4;
    const float4 r0 = *(const float4*)(W + (size_t)(2 * kp) * N + nc);
    const float4 r1 = *(const float4*)(W + (size_t)(2 * kp + 1) * N + nc);
    uint32_t h0,l0,h1,l1,h2,l2,h3,l3;
    split2(r0.x, r1.x, h0, l0);
    split2(r0.y, r1.y, h1, l1);
    split2(r0.z, r1.z, h2, l2);
    split2(r0.w, r1.w, h3, l3);
    size_t o = (size_t)kp * N + nc;
    *(uint4*)(Wh + o) = make_uint4(h0, h1, h2, h3);
    *(uint4*)(Wl + o) = make_uint4(l0, l1, l2, l3);
}

// ---------------------------------------------------------------------------
__device__ __forceinline__ float2 block_reduce2_256(float a, float b) {
    #pragma unroll
    for (int o = 16; o > 0; o >>= 1) {
        a += __shfl_xor_sync(0xffffffffu, a, o);
        b += __shfl_xor_sync(0xffffffffu, b, o);
    }
    __shared__ float sa[8], sb[8];
    int w = threadIdx.x >> 5, lane = threadIdx.x & 31;
    __syncthreads();
    if (lane == 0) { sa[w] = a; sb[w] = b; }
    __syncthreads();
    float ta = 0.f, tb = 0.f;
    #pragma unroll
    for (int i = 0; i < 8; i++) { ta += sa[i]; tb += sb[i]; }
    return make_float2(ta, tb);
}

__global__ __launch_bounds__(256) void ln_kernel(
    const float* __restrict__ in, const float* __restrict__ g,
    const float* __restrict__ b,
    uint32_t* __restrict__ outH, uint32_t* __restrict__ outL)
{
    int row = blockIdx.x;
    int t = threadIdx.x;
    const float4 v = ((const float4*)(in + (size_t)row * DMODEL))[t];
    float s = v.x + v.y + v.z + v.w;
    float q = v.x*v.x + v.y*v.y + v.z*v.z + v.w*v.w;
    float2 r = block_reduce2_256(s, q);
    const float inv_n = 1.0f / DMODEL;
    float mu  = r.x * inv_n;
    float var = r.y * inv_n - mu * mu;
    float inv = rsqrtf(var + 1e-5f);
    const float4 gg = ((const float4*)g)[t];
    const float4 bb = ((const float4*)b)[t];
    float o0 = (v.x - mu) * inv * gg.x + bb.x;
    float o1 = (v.y - mu) * inv * gg.y + bb.y;
    float o2 = (v.z - mu) * inv * gg.z + bb.z;
    float o3 = (v.w - mu) * inv * gg.w + bb.w;
    uint32_t h0,l0,h1,l1;
    split2(o0, o1, h0, l0);
    split2(o2, o3, h1, l1);
    ((uint2*)(outH + (size_t)row * 512))[t] = make_uint2(h0, h1);
    ((uint2*)(outL + (size_t)row * 512))[t] = make_uint2(l0, l1);
}

__global__ __launch_bounds__(256) void dln_kernel(
    const float* __restrict__ in,
    const float* __restrict__ g1, const float* __restrict__ b1,
    const float* __restrict__ sc,
    const float* __restrict__ g2, const float* __restrict__ b2,
    uint32_t* __restrict__ outH, uint32_t* __restrict__ outL)
{
    int row = blockIdx.x;
    int t = threadIdx.x;
    const float inv_n = 1.0f / DMODEL;
    const float4 v = ((const float4*)(in + (size_t)row * DMODEL))[t];
    float s = v.x + v.y + v.z + v.w;
    float q = v.x*v.x + v.y*v.y + v.z*v.z + v.w*v.w;
    float2 r = block_reduce2_256(s, q);
    float mu  = r.x * inv_n;
    float var = r.y * inv_n - mu * mu;
    float inv = rsqrtf(var + 1e-5f);
    const float4 gg1 = ((const float4*)g1)[t];
    const float4 bb1 = ((const float4*)b1)[t];
    const float4 sc4 = ((const float4*)sc)[t];
    float4 tv;
    tv.x = ((v.x - mu) * inv * gg1.x + bb1.x) * sc4.x;
    tv.y = ((v.y - mu) * inv * gg1.y + bb1.y) * sc4.y;
    tv.z = ((v.z - mu) * inv * gg1.z + bb1.z) * sc4.z;
    tv.w = ((v.w - mu) * inv * gg1.w + bb1.w) * sc4.w;
    float s2 = tv.x + tv.y + tv.z + tv.w;
    float q2 = tv.x*tv.x + tv.y*tv.y + tv.z*tv.z + tv.w*tv.w;
    float2 r2 = block_reduce2_256(s2, q2);
    float mu2  = r2.x * inv_n;
    float var2 = r2.y * inv_n - mu2 * mu2;
    float inv2 = rsqrtf(var2 + 1e-5f);
    const float4 gg2 = ((const float4*)g2)[t];
    const float4 bb2 = ((const float4*)b2)[t];
    float o0 = (tv.x - mu2) * inv2 * gg2.x + bb2.x;
    float o1 = (tv.y - mu2) * inv2 * gg2.y + bb2.y;
    float o2 = (tv.z - mu2) * inv2 * gg2.z + bb2.z;
    float o3 = (tv.w - mu2) * inv2 * gg2.w + bb2.w;
    uint32_t h0,l0,h1,l1;
    split2(o0, o1, h0, l0);
    split2(o2, o3, h1, l1);
    ((uint2*)(outH + (size_t)row * 512))[t] = make_uint2(h0, h1);
    ((uint2*)(outL + (size_t)row * 512))[t] = make_uint2(l0, l1);
}

// ---------------------------------------------------------------------------
// bf16x3 GEMM: R8 tile/fragments/epilogue, 3-stage cp.async ring (1 sync/ktile)
// A: pair-packed [M][ldap]. B: pair-packed [K/2][N].
// Dynamic smem layout (u32):
//   AhS[3][128][20] @0   AlS @7680   BhS[3][16][136] @15360   BlS @21888
// ---------------------------------------------------------------------------
#define A_ST   2560                      // 128*20 per stage
#define B_ST   2176                      // 16*136 per stage
#define OFF_AL (3 * A_ST)                // 7680
#define OFF_BH (2 * 3 * A_ST)            // 15360
#define OFF_BL (OFF_BH + 3 * B_ST)       // 21888
#define GEMM_SMEM_U32 (OFF_BL + 3 * B_ST)  // 28416 u32
#define GEMM_SMEM_B   (GEMM_SMEM_U32 * 4)  // 113664 B

__global__ __launch_bounds__(256, 2) void gemm_ps_kernel(
    const uint32_t* __restrict__ Ah, const uint32_t* __restrict__ Al, int ldap,
    const uint32_t* __restrict__ Bh, const uint32_t* __restrict__ Bl,
    const float* __restrict__ bias, const float* __restrict__ cscale,
    float* __restrict__ Cf, uint32_t* __restrict__ Ch, uint32_t* __restrict__ Cl,
    int qscaleCols, int M, int N, int K)
{
    extern __shared__ uint32_t sm[];
    uint32_t* AhS = sm;
    uint32_t* AlS = sm + OFF_AL;
    uint32_t* BhS = sm + OFF_BH;
    uint32_t* BlS = sm + OFF_BL;

    const int tid  = threadIdx.x;
    const int warp = tid >> 5;
    const int lane = tid & 31;
    const int wm = (warp & 3) * 32;
    const int wn = (warp >> 2) * 64;
    const int q  = lane >> 2;
    const int r  = lane & 3;

    const int rowBase = blockIdx.y * 128;
    const int colBase = blockIdx.x * 128;

    const int arow0 = tid >> 2;
    const int acc0  = (tid & 3) * 4;
    const int bkp0  = tid >> 5;
    const int bcc0  = (tid & 31) * 4;

    const int nt = K >> 5;

    auto issue = [&](int st, int bb) {
        int kp0 = st * 16;
        #pragma unroll
        for (int it = 0; it < 2; it++) {
            int row = arow0 + 64 * it;
            size_t src = (size_t)(rowBase + row) * ldap + kp0 + acc0;
            int d = bb * A_ST + row * 20 + acc0;
            CP16(smem_addr_u32(&AhS[d]), Ah + src);
            CP16(smem_addr_u32(&AlS[d]), Al + src);
        }
        #pragma unroll
        for (int it = 0; it < 2; it++) {
            int kp = bkp0 + 8 * it;
            size_t src = (size_t)(kp0 + kp) * N + colBase + bcc0;
            int d = bb * B_ST + kp * 136 + bcc0;
            CP16(smem_addr_u32(&BhS[d]), Bh + src);
            CP16(smem_addr_u32(&BlS[d]), Bl + src);
        }
        CP_COMMIT();
    };

    float c[2][8][4];
    #pragma unroll
    for (int mf = 0; mf < 2; mf++)
        #pragma unroll
        for (int nf = 0; nf < 8; nf++)
            #pragma unroll
            for (int e = 0; e < 4; e++) c[mf][nf][e] = 0.f;

    issue(0, 0);
    if (nt > 1) issue(1, 1);

    for (int i = 0; i < nt; i++) {
        const int bb = i % 3;
        if (i + 1 < nt) { CP_WAIT1(); } else { CP_WAIT0(); }
        __syncthreads();
        if (i + 2 < nt) issue(i + 2, (i + 2) % 3);

        const uint32_t* Abh = AhS + bb * A_ST;
        const uint32_t* Abl = AlS + bb * A_ST;
        const uint32_t* Bbh = BhS + bb * B_ST;
        const uint32_t* Bbl = BlS + bb * B_ST;

        #pragma unroll
        for (int ks = 0; ks < 2; ks++) {
            const int kk2 = ks * 8;
            uint32_t ah[2][4], al[2][4];
            #pragma unroll
            for (int mf = 0; mf < 2; mf++) {
                int m0 = wm + mf * 16 + q;
                ah[mf][0] = Abh[m0 * 20 + kk2 + r];
                ah[mf][1] = Abh[(m0 + 8) * 20 + kk2 + r];
                ah[mf][2] = Abh[m0 * 20 + kk2 + 4 + r];
                ah[mf][3] = Abh[(m0 + 8) * 20 + kk2 + 4 + r];
                al[mf][0] = Abl[m0 * 20 + kk2 + r];
                al[mf][1] = Abl[(m0 + 8) * 20 + kk2 + r];
                al[mf][2] = Abl[m0 * 20 + kk2 + 4 + r];
                al[mf][3] = Abl[(m0 + 8) * 20 + kk2 + 4 + r];
            }
            #pragma unroll
            for (int nf = 0; nf < 8; nf++) {
                int n = wn + nf * 8 + q;
                uint32_t bh0 = Bbh[(kk2 + r) * 136 + n];
                uint32_t bh1 = Bbh[(kk2 + 4 + r) * 136 + n];
                uint32_t bl0 = Bbl[(kk2 + r) * 136 + n];
                uint32_t bl1 = Bbl[(kk2 + 4 + r) * 136 + n];
                #pragma unroll
                for (int mf = 0; mf < 2; mf++) {
                    mma_bf16(c[mf][nf], ah[mf], bh0, bh1);
                    mma_bf16(c[mf][nf], al[mf], bh0, bh1);
                    mma_bf16(c[mf][nf], ah[mf], bl0, bl1);
                }
            }
        }
        // single sync per k-tile: stage(i+2) targets buffer (i-1)%3, whose
        // compute finished before this iteration's leading __syncthreads.
    }

    // ---- epilogue (verbatim R8) ----
    #pragma unroll
    for (int mf = 0; mf < 2; mf++) {
        int row0 = rowBase + wm + mf * 16 + q;
        #pragma unroll
        for (int half = 0; half < 2; half++) {
            int row = row0 + half * 8;
            #pragma unroll
            for (int nf = 0; nf < 8; nf++) {
                int col = colBase + wn + nf * 8 + r * 2;
                float v0 = c[mf][nf][half * 2 + 0];
                float v1 = c[mf][nf][half * 2 + 1];
                if (bias)   { v0 += bias[col];   v1 += bias[col + 1]; }
                if (col < qscaleCols) { v0 *= 0.125f; v1 *= 0.125f; }
                if (Cf) {
                    if (cscale) { v0 *= cscale[col]; v1 *= cscale[col + 1]; }
                    *(float2*)(Cf + (size_t)row * N + col) = make_float2(v0, v1);
                } else {
                    uint32_t hh, ll;
                    split2(v0, v1, hh, ll);
                    size_t off = (size_t)row * (N >> 1) + (col >> 1);
                    Ch[off] = hh;
                    Cl[off] = ll;
                }
            }
        }
    }
}

// ---------------------------------------------------------------------------
// bf16x3 HMMA flash attention (validated R8, unchanged).
// ---------------------------------------------------------------------------
__global__ __launch_bounds__(256) void attn_tc_kernel(
    const uint32_t* __restrict__ qkvh, const uint32_t* __restrict__ qkvl,
    uint32_t* __restrict__ outH, uint32_t* __restrict__ outL)
{
    __shared__ uint32_t KpH[64][36];
    __shared__ uint32_t KpL[64][36];
    __shared__ uint32_t VpH[32][72];
    __shared__ uint32_t VpL[32][72];

    const int bh = blockIdx.y;
    const int b  = bh >> 4;
    const int h  = bh & 15;
    const int tid  = threadIdx.x;
    const int warp = tid >> 5;
    const int lane = tid & 31;
    const int q = lane >> 2;
    const int r = lane & 3;

    const int qrow = blockIdx.x * 128 + warp * 16;

    uint32_t qh[4][4], ql[4][4];
    {
        const uint32_t* Q0h = qkvh + (size_t)(b * SEQ + qrow + q) * 1536 + 32 * h;
        const uint32_t* Q1h = Q0h + 8 * 1536;
        const uint32_t* Q0l = qkvl + (size_t)(b * SEQ + qrow + q) * 1536 + 32 * h;
        const uint32_t* Q1l = Q0l + 8 * 1536;
        #pragma unroll
        for (int ks = 0; ks < 4; ks++) {
            int p = 8 * ks + r;
            qh[ks][0] = Q0h[p];     qh[ks][1] = Q1h[p];
            qh[ks][2] = Q0h[p + 4]; qh[ks][3] = Q1h[p + 4];
            ql[ks][0] = Q0l[p];     ql[ks][1] = Q1l[p];
            ql[ks][2] = Q0l[p + 4]; ql[ks][3] = Q1l[p + 4];
        }
    }

    float o[8][4];
    #pragma unroll
    for (int nf = 0; nf < 8; nf++)
        #pragma unroll
        for (int e = 0; e < 4; e++) o[nf][e] = 0.f;
    float m0 = -1e30f, m1 = -1e30f;
    float l0 = 0.f, l1 = 0.f;

    const size_t baseK = (size_t)(b * SEQ) * 1536 + 512 + 32 * h;
    const size_t baseV = (size_t)(b * SEQ) * 1536 + 1024 + 32 * h;

    for (int j0 = 0; j0 < SEQ; j0 += 64) {
        __syncthreads();
        #pragma unroll
        for (int it = 0; it < 2; it++) {
            int idx = tid + it * 256;
            int key = idx >> 3;
            int c   = (idx & 7) * 4;
            size_t src = baseK + (size_t)(j0 + key) * 1536 + c;
            *(uint4*)&KpH[key][c] = *(const uint4*)(qkvh + src);
            *(uint4*)&KpL[key][c] = *(const uint4*)(qkvl + src);
        }
        #pragma unroll
        for (int it = 0; it < 2; it++) {
            int idx = tid + it * 256;
            int kp  = idx >> 4;
            int dpp = (idx & 15) * 2;
            size_t src = baseV + (size_t)(j0 + 2 * kp) * 1536 + dpp;
            uint2 aH = *(const uint2*)(qkvh + src);
            uint2 bH = *(const uint2*)(qkvh + src + 1536);
            uint2 aL = *(const uint2*)(qkvl + src);
            uint2 bL = *(const uint2*)(qkvl + src + 1536);
            VpH[kp][2*dpp    ] = __byte_perm(aH.x, bH.x, 0x5410);
            VpH[kp][2*dpp + 1] = __byte_perm(aH.x, bH.x, 0x7632);
            VpH[kp][2*dpp + 2] = __byte_perm(aH.y, bH.y, 0x5410);
            VpH[kp][2*dpp + 3] = __byte_perm(aH.y, bH.y, 0x7632);
            VpL[kp][2*dpp    ] = __byte_perm(aL.x, bL.x, 0x5410);
            VpL[kp][2*dpp + 1] = __byte_perm(aL.x, bL.x, 0x7632);
            VpL[kp][2*dpp + 2] = __byte_perm(aL.y, bL.y, 0x5410);
            VpL[kp][2*dpp + 3] = __byte_perm(aL.y, bL.y, 0x7632);
        }
        __syncthreads();

        float s[8][4];
        #pragma unroll
        for (int nf = 0; nf < 8; nf++)
            #pragma unroll
            for (int e = 0; e < 4; e++) s[nf][e] = 0.f;

        #pragma unroll
        for (int ks = 0; ks < 4; ks++) {
            #pragma unroll
            for (int nf = 0; nf < 8; nf++) {
                int key = 8 * nf + q;
                uint32_t bh0 = KpH[key][8 * ks + r];
                uint32_t bh1 = KpH[key][8 * ks + r + 4];
                uint32_t bl0 = KpL[key][8 * ks + r];
                uint32_t bl1 = KpL[key][8 * ks + r + 4];
                mma_bf16(s[nf], qh[ks], bh0, bh1);
                mma_bf16(s[nf], ql[ks], bh0, bh1);
                mma_bf16(s[nf], qh[ks], bl0, bl1);
            }
        }

        float t0 = -1e30f, t1 = -1e30f;
        #pragma unroll
        for (int nf = 0; nf < 8; nf++) {
            t0 = fmaxf(t0, fmaxf(s[nf][0], s[nf][1]));
            t1 = fmaxf(t1, fmaxf(s[nf][2], s[nf][3]));
        }
        t0 = fmaxf(t0, __shfl_xor_sync(0xffffffffu, t0, 1));
        t0 = fmaxf(t0, __shfl_xor_sync(0xffffffffu, t0, 2));
        t1 = fmaxf(t1, __shfl_xor_sync(0xffffffffu, t1, 1));
        t1 = fmaxf(t1, __shfl_xor_sync(0xffffffffu, t1, 2));

        float mn0 = fmaxf(m0, t0), mn1 = fmaxf(m1, t1);
        float a0 = __expf(m0 - mn0), a1 = __expf(m1 - mn1);
        m0 = mn0; m1 = mn1;
        l0 *= a0; l1 *= a1;
        #pragma unroll
        for (int nf = 0; nf < 8; nf++) {
            o[nf][0] *= a0; o[nf][1] *= a0;
            o[nf][2] *= a1; o[nf][3] *= a1;
        }

        uint32_t pah[4][4], pal[4][4];
        float sum0 = 0.f, sum1 = 0.f;
        #pragma unroll
        for (int nf = 0; nf < 8; nf++) {
            float p0 = __expf(s[nf][0] - m0);
            float p1 = __expf(s[nf][1] - m0);
            float p2 = __expf(s[nf][2] - m1);
            float p3 = __expf(s[nf][3] - m1);
            sum0 += p0 + p1; sum1 += p2 + p3;
            int ks = nf >> 1, part = nf & 1;
            split2(p0, p1, pah[ks][2 * part],     pal[ks][2 * part]);
            split2(p2, p3, pah[ks][2 * part + 1], pal[ks][2 * part + 1]);
        }
        sum0 += __shfl_xor_sync(0xffffffffu, sum0, 1);
        sum0 += __shfl_xor_sync(0xffffffffu, sum0, 2);
        sum1 += __shfl_xor_sync(0xffffffffu, sum1, 1);
        sum1 += __shfl_xor_sync(0xffffffffu, sum1, 2);
        l0 += sum0; l1 += sum1;

        #pragma unroll
        for (int ks = 0; ks < 4; ks++) {
            #pragma unroll
            for (int nf = 0; nf < 8; nf++) {
                int d = 8 * nf + q;
                uint32_t bh0 = VpH[8 * ks + r    ][d];
                uint32_t bh1 = VpH[8 * ks + r + 4][d];
                uint32_t bl0 = VpL[8 * ks + r    ][d];
                uint32_t bl1 = VpL[8 * ks + r + 4][d];
                mma_bf16(o[nf], pah[ks], bh0, bh1);
                mma_bf16(o[nf], pal[ks], bh0, bh1);
                mma_bf16(o[nf], pah[ks], bl0, bl1);
            }
        }
    }

    float inv0 = 1.0f / l0, inv1 = 1.0f / l1;
    uint32_t* O0h = outH + (size_t)(b * SEQ + qrow + q) * 512 + 32 * h;
    uint32_t* O0l = outL + (size_t)(b * SEQ + qrow + q) * 512 + 32 * h;
    uint32_t* O1h = O0h + 8 * 512;
    uint32_t* O1l = O0l + 8 * 512;
    #pragma unroll
    for (int nf = 0; nf < 8; nf++) {
        int pc = 4 * nf + r;
        uint32_t hh, ll;
        split2(o[nf][0] * inv0, o[nf][1] * inv0, hh, ll);
        O0h[pc] = hh; O0l[pc] = ll;
        split2(o[nf][2] * inv1, o[nf][3] * inv1, hh, ll);
        O1h[pc] = hh; O1l[pc] = ll;
    }
}

// ---------------------------------------------------------------------------
// GeGLU: read u fp32, write a*gelu(g) pair-packed (row stride 2048 pairs)
// ---------------------------------------------------------------------------
__global__ __launch_bounds__(256) void geglu_kernel(
    const float* __restrict__ u,
    uint32_t* __restrict__ outH, uint32_t* __restrict__ outL)
{
    int i = blockIdx.x * 256 + threadIdx.x;
    int row = i >> 10;
    int c4  = i & 1023;
    const float4* base = (const float4*)(u + (size_t)row * (2 * FFDIM));
    float4 a = base[c4];
    float4 g = base[c4 + 1024];
    float o0 = a.x * g.x * normcdff(g.x);
    float o1 = a.y * g.y * normcdff(g.y);
    float o2 = a.z * g.z * normcdff(g.z);
    float o3 = a.w * g.w * normcdff(g.w);
    uint32_t h0,l0,h1,l1;
    split2(o0, o1, h0, l0);
    split2(o2, o3, h1, l1);
    ((uint2*)(outH + (size_t)row * 2048))[c4] = make_uint2(h0, h1);
    ((uint2*)(outL + (size_t)row * 2048))[c4] = make_uint2(l0, l1);
}

// ---------------------------------------------------------------------------
extern "C" void kernel_launch(void* const* d_in, const int* in_sizes, int n_in,
                              void* d_out, int out_size)
{
    const float* x            = (const float*)d_in[0];
    const float* w_qkv        = (const float*)d_in[2];
    const float* w_out        = (const float*)d_in[3];
    const float* b_out        = (const float*)d_in[4];
    const float* ln_inner_g   = (const float*)d_in[5];
    const float* ln_inner_b   = (const float*)d_in[6];
    const float* ln_pre_attn_g= (const float*)d_in[7];
    const float* ln_pre_attn_b= (const float*)d_in[8];
    const float* scale_attn   = (const float*)d_in[9];
    const float* w1           = (const float*)d_in[10];
    const float* b1           = (const float*)d_in[11];
    const float* w2           = (const float*)d_in[12];
    const float* b2           = (const float*)d_in[13];
    const float* ln_pre_ff_g  = (const float*)d_in[14];
    const float* ln_pre_ff_b  = (const float*)d_in[15];
    const float* scale_ff     = (const float*)d_in[16];
    float* out = (float*)d_out;

    uint32_t *whP, *wlP, *ahP, *alP, *qhP, *qlP;
    float *uP, *pP;
    cudaGetSymbolAddress((void**)&whP, g_wh);
    cudaGetSymbolAddress((void**)&wlP, g_wl);
    cudaGetSymbolAddress((void**)&ahP, g_ah);
    cudaGetSymbolAddress((void**)&alP, g_al);
    cudaGetSymbolAddress((void**)&qhP, g_qh);
    cudaGetSymbolAddress((void**)&qlP, g_ql);
    cudaGetSymbolAddress((void**)&uP,  g_u);
    cudaGetSymbolAddress((void**)&pP,  g_p);

    cudaFuncSetAttribute(gemm_ps_kernel,
                         cudaFuncAttributeMaxDynamicSharedMemorySize, GEMM_SMEM_B);

    // 0) split weights into pair-packed bf16 hi/lo
    {
        int t;
        t = 512 * (3072 / 4);
        split_w_kernel<<<(t + 255) / 256, 256>>>(w_qkv, whP + OFF_WQKV, wlP + OFF_WQKV, 3072, t);
        t = 512 * (1024 / 4);
        split_w_kernel<<<(t + 255) / 256, 256>>>(w_out, whP + OFF_WOUT, wlP + OFF_WOUT, 1024, t);
        t = 512 * (8192 / 4);
        split_w_kernel<<<(t + 255) / 256, 256>>>(w1, whP + OFF_W1, wlP + OFF_W1, 8192, t);
        t = 2048 * (1024 / 4);
        split_w_kernel<<<(t + 255) / 256, 256>>>(w2, whP + OFF_W2, wlP + OFF_W2, 1024, t);
    }

    // 1) h = LN_pre_attn(x) -> packed
    ln_kernel<<<NTOK, 256>>>(x, ln_pre_attn_g, ln_pre_attn_b, ahP, alP);

    // 2) qkv = h @ w_qkv -> packed (Q cols pre-scaled by 0.125)
    gemm_ps_kernel<<<dim3(3072/128, NTOK/128), 256, GEMM_SMEM_B>>>(
        ahP, alP, 512, whP + OFF_WQKV, wlP + OFF_WQKV,
        nullptr, nullptr, nullptr, qhP, qlP, 1024, NTOK, 3072, DMODEL);

    // 3) attention -> packed g_ah/g_al
    attn_tc_kernel<<<dim3(SEQ/128, 2 * NHEAD), 256>>>(qhP, qlP, ahP, alP);

    // 4) proj = attn @ w_out + b_out -> fp32 g_p
    gemm_ps_kernel<<<dim3(DMODEL/128, NTOK/128), 256, GEMM_SMEM_B>>>(
        ahP, alP, 512, whP + OFF_WOUT, wlP + OFF_WOUT,
        b_out, nullptr, pP, nullptr, nullptr, 0, NTOK, DMODEL, DMODEL);

    // 5) h2 = LN_pre_ff(LN_inner(p) * scale_attn) -> packed
    dln_kernel<<<NTOK, 256>>>(pP, ln_inner_g, ln_inner_b, scale_attn,
                              ln_pre_ff_g, ln_pre_ff_b, ahP, alP);

    // 6) u = h2 @ w1 + b1 -> fp32 g_u
    gemm_ps_kernel<<<dim3(2*FFDIM/128, NTOK/128), 256, GEMM_SMEM_B>>>(
        ahP, alP, 512, whP + OFF_W1, wlP + OFF_W1,
        b1, nullptr, uP, nullptr, nullptr, 0, NTOK, 2 * FFDIM, DMODEL);

    // 7) GeGLU -> packed (row stride 2048 pairs)
    geglu_kernel<<<(NTOK * (FFDIM/4)) / 256, 256>>>(uP, ahP, alP);

    // 8) out = geglu @ w2 + b2, * scale_ff -> d_out
    gemm_ps_kernel<<<dim3(DMODEL/128, NTOK/128), 256, GEMM_SMEM_B>>>(
        ahP, alP, 2048, whP + OFF_W2, wlP + OFF_W2,
        b2, scale_ff, out, nullptr, nullptr, 0, NTOK, DMODEL, FFDIM);
}